// round 4
// baseline (speedup 1.0000x reference)
#include <cuda_runtime.h>
#include <math.h>

#define BB 2
#define DIMC 96
#define INNER 192
#define NH 48
#define DH 4
#define SS 576
#define GTOT (BB*SS)   // 1152
#define F3 (3*INNER)   // 576
#define NBH (BB*NH)    // 96

// Scratch (device globals; no allocation allowed)
__device__ float g_xi[GTOT * 2 * INNER];    // up-proj output (x_mlstm | z)
__device__ float g_xconv[GTOT * INNER];     // silu(causal conv)
__device__ float g_qkv[GTOT * F3];          // [q | k | v] position-major (for gates)
__device__ float4 g_q4[NBH * SS];           // head-major q
__device__ float4 g_k4[NBH * SS];           // head-major k
__device__ float4 g_v4[NBH * SS];           // head-major v
__device__ float g_ig[NBH * SS];
__device__ float g_fg[NBH * SS];
__device__ float g_a[NBH * SS];             // ig - lf_cum
__device__ float2 g_cm[NBH * SS];           // (M = prefmax a, cums = lf_cum[s+1])
__device__ float g_hnorm[GTOT * INNER];

// ---------------------------------------------------------------------------
// K1: LayerNorm over C=96 + up-projection to 384. 8 positions per block.
// 384 threads = 192 output-pairs (o, o+192) x 2 c-slices of 48.
// ---------------------------------------------------------------------------
__global__ void k1_ln_up(const float* __restrict__ x,
                         const float* __restrict__ ln_g,
                         const float* __restrict__ ln_b,
                         const float* __restrict__ w_up,
                         const float* __restrict__ b_up) {
    __shared__ float h[8][DIMC];
    __shared__ float mu[8], iv[8];
    __shared__ float part[8][2][384];      // 24.6KB
    const int g0 = blockIdx.x * 8;
    const int b = g0 / SS, s0 = g0 % SS;
    const int tid = threadIdx.x;           // 384

    for (int i = tid; i < 8 * DIMC; i += 384) {
        int c = i >> 3, p = i & 7;
        h[p][c] = x[(b * DIMC + c) * SS + s0 + p];
    }
    __syncthreads();
    if (tid < 256) {
        int p = tid >> 5, lane = tid & 31;
        float sum = 0.f, sq = 0.f;
        for (int c = lane; c < DIMC; c += 32) { float v = h[p][c]; sum += v; sq += v * v; }
#pragma unroll
        for (int off = 16; off > 0; off >>= 1) {
            sum += __shfl_down_sync(0xffffffffu, sum, off);
            sq  += __shfl_down_sync(0xffffffffu, sq, off);
        }
        if (lane == 0) {
            float m = sum * (1.f / DIMC);
            float var = sq * (1.f / DIMC) - m * m;
            mu[p] = m;
            iv[p] = rsqrtf(var + 1e-5f);
        }
    }
    __syncthreads();
    for (int i = tid; i < 8 * DIMC; i += 384) {
        int c = i >> 3, p = i & 7;
        h[p][c] = (h[p][c] - mu[p]) * iv[p] * ln_g[c] + ln_b[c];
    }
    __syncthreads();

    const int o0 = tid % 192;
    const int o1 = o0 + 192;
    const int slice = tid / 192;           // 0..1, 48 c each
    const float* w0 = w_up + o0 * DIMC + slice * 48;
    const float* w1 = w_up + o1 * DIMC + slice * 48;
    float acc0[8], acc1[8];
#pragma unroll
    for (int p = 0; p < 8; p++) { acc0[p] = 0.f; acc1[p] = 0.f; }
    for (int c = 0; c < 48; c++) {
        float wa = w0[c], wb = w1[c];
        int cc = slice * 48 + c;
#pragma unroll
        for (int p = 0; p < 8; p++) {
            float hv = h[p][cc];
            acc0[p] += wa * hv;
            acc1[p] += wb * hv;
        }
    }
#pragma unroll
    for (int p = 0; p < 8; p++) { part[p][slice][o0] = acc0[p]; part[p][slice][o1] = acc1[p]; }
    __syncthreads();
#pragma unroll
    for (int j = 0; j < 8; j++) {
        int idx = tid + j * 384;           // 0..3071
        int o2 = idx % 384, p2 = idx / 384;
        float v = part[p2][0][o2] + part[p2][1][o2] + b_up[o2];
        g_xi[(g0 + p2) * (2 * INNER) + o2] = v;
    }
}

// ---------------------------------------------------------------------------
// K23: fused causal depthwise conv (K=4) + SiLU + per-head 4x4 q/k/v
// one thread per (position, head); writes position-major AND head-major.
// ---------------------------------------------------------------------------
__global__ void k23_conv_qkv(const float* __restrict__ w_conv,
                             const float* __restrict__ b_conv,
                             const float* __restrict__ w_q, const float* __restrict__ b_q,
                             const float* __restrict__ w_k, const float* __restrict__ b_k,
                             const float* __restrict__ w_v, const float* __restrict__ b_v) {
    int t = blockIdx.x * 256 + threadIdx.x;
    if (t >= GTOT * NH) return;
    int n = t % NH;
    int g = t / NH;
    int s = g % SS;
    int b = g / SS;

    float xc[4];
    float4 xm = make_float4(0.f, 0.f, 0.f, 0.f);
#pragma unroll
    for (int d = 0; d < 4; d++) xc[d] = b_conv[n * 4 + d];
#pragma unroll
    for (int k = 0; k < 4; k++) {
        int sp = s - 3 + k;
        if (sp >= 0) {
            float4 xk = *(const float4*)(g_xi + (g - 3 + k) * (2 * INNER) + n * 4);
            if (k == 3) xm = xk;
#pragma unroll
            for (int d = 0; d < 4; d++)
                xc[d] += w_conv[(n * 4 + d) * 4 + k] * ((const float*)&xk)[d];
        }
    }
#pragma unroll
    for (int d = 0; d < 4; d++) {
        float sg = 1.f / (1.f + __expf(-xc[d]));
        xc[d] *= sg;
    }
    *(float4*)(g_xconv + g * INNER + n * 4) = make_float4(xc[0], xc[1], xc[2], xc[3]);

    float q[4], k4_[4], v[4];
#pragma unroll
    for (int o = 0; o < 4; o++) {
        const float* wq = w_q + n * 16 + o * 4;
        q[o] = b_q[n * 4 + o] + wq[0] * xc[0] + wq[1] * xc[1] + wq[2] * xc[2] + wq[3] * xc[3];
        const float* wk = w_k + n * 16 + o * 4;
        k4_[o] = b_k[n * 4 + o] + wk[0] * xc[0] + wk[1] * xc[1] + wk[2] * xc[2] + wk[3] * xc[3];
        const float* wv = w_v + n * 16 + o * 4;
        v[o] = b_v[n * 4 + o] + wv[0] * xm.x + wv[1] * xm.y + wv[2] * xm.z + wv[3] * xm.w;
    }
    float4 qf = make_float4(q[0], q[1], q[2], q[3]);
    float4 kf = make_float4(k4_[0], k4_[1], k4_[2], k4_[3]);
    float4 vf = make_float4(v[0], v[1], v[2], v[3]);
    float* out = g_qkv + g * F3;
    *(float4*)(out + n * 4)             = qf;
    *(float4*)(out + INNER + n * 4)     = kf;
    *(float4*)(out + 2 * INNER + n * 4) = vf;
    int hidx = (b * NH + n) * SS + s;
    g_q4[hidx] = qf;
    g_k4[hidx] = kf;
    g_v4[hidx] = vf;
}

// ---------------------------------------------------------------------------
// K3b v3: gate pre-activations. 8 positions per block.
// 384 threads = 48 heads (ig+fg pair share activations) x 8 f-slices of 72.
// ---------------------------------------------------------------------------
__global__ void k3b_gates(const float* __restrict__ w_ig, const float* __restrict__ b_ig,
                          const float* __restrict__ w_fg, const float* __restrict__ b_fg) {
    __shared__ float sq[8 * F3];            // 18KB
    __shared__ float part_i[8][8][48];      // 12.3KB
    __shared__ float part_f[8][8][48];      // 12.3KB
    const int g0 = blockIdx.x * 8;
    const int tid = threadIdx.x;            // 384
    for (int i = tid; i < 8 * F3; i += 384)
        sq[i] = g_qkv[g0 * F3 + i];
    __syncthreads();

    const int n = tid % 48;
    const int slice = tid / 48;             // 0..7, 72 f each
    const int f0 = slice * 72;
    const float* wi = w_ig + n * F3 + f0;
    const float* wf = w_fg + n * F3 + f0;
    float ai[8], af[8];
#pragma unroll
    for (int p = 0; p < 8; p++) { ai[p] = 0.f; af[p] = 0.f; }
    for (int f = 0; f < 72; f++) {
        float wiv = wi[f], wfv = wf[f];
#pragma unroll
        for (int p = 0; p < 8; p++) {
            float s = sq[p * F3 + f0 + f];
            ai[p] += wiv * s;
            af[p] += wfv * s;
        }
    }
#pragma unroll
    for (int p = 0; p < 8; p++) { part_i[p][slice][n] = ai[p]; part_f[p][slice][n] = af[p]; }
    __syncthreads();

    const int b = g0 / SS, s0 = g0 % SS;
#pragma unroll
    for (int j = 0; j < 2; j++) {
        int idx = tid + j * 384;            // 0..767
        int r2 = idx % 96, p2 = idx / 96;
        bool ii = r2 < NH;
        int n2 = ii ? r2 : r2 - NH;
        float v = 0.f;
#pragma unroll
        for (int sl = 0; sl < 8; sl++)
            v += ii ? part_i[p2][sl][n2] : part_f[p2][sl][n2];
        v += ii ? b_ig[n2] : b_fg[n2];
        float* dst = ii ? g_ig : g_fg;
        dst[(b * NH + n2) * SS + s0 + p2] = v;
    }
}

// ---------------------------------------------------------------------------
// K4a: per-head scans. One block per (b,head), thread s.
//   cums[s] = lf_cum[s+1] (prefix sum of logsigmoid(fg))
//   a[s]    = ig[s] - cums[s]
//   M[s]    = max_{t<=s} a[t]  (prefix max)
// ---------------------------------------------------------------------------
__global__ void k4a_scan() {
    __shared__ float warpsum[18];
    __shared__ float warpmax[18];
    const int bh = blockIdx.x;
    const int s = threadIdx.x;
    const int wid = s >> 5, lane = s & 31;

    float fgv = g_fg[bh * SS + s];
    float igv = g_ig[bh * SS + s];
    float logf = (fgv > 0.f) ? -log1pf(__expf(-fgv)) : (fgv - log1pf(__expf(fgv)));

    float v = logf;
#pragma unroll
    for (int off = 1; off < 32; off <<= 1) {
        float nn = __shfl_up_sync(0xffffffffu, v, off);
        if (lane >= off) v += nn;
    }
    if (lane == 31) warpsum[wid] = v;
    __syncthreads();
    if (s == 0) {
        float acc = 0.f;
#pragma unroll
        for (int w = 0; w < 18; w++) { acc += warpsum[w]; warpsum[w] = acc; }
    }
    __syncthreads();
    const float cums = v + (wid > 0 ? warpsum[wid - 1] : 0.f);
    const float a = igv - cums;

    float m = a;
#pragma unroll
    for (int off = 1; off < 32; off <<= 1) {
        float nn = __shfl_up_sync(0xffffffffu, m, off);
        if (lane >= off) m = fmaxf(m, nn);
    }
    __syncthreads();   // warpsum reuse barrier
    if (lane == 31) warpmax[wid] = m;
    __syncthreads();
    if (s == 0) {
        float acc = -1e30f;
#pragma unroll
        for (int w = 0; w < 18; w++) { acc = fmaxf(acc, warpmax[w]); warpmax[w] = acc; }
    }
    __syncthreads();
    const float M = (wid > 0) ? fmaxf(m, warpmax[wid - 1]) : m;

    g_a[bh * SS + s] = a;
    g_cm[bh * SS + s] = make_float2(M, cums);
}

// ---------------------------------------------------------------------------
// K4b: mLSTM main compute, warp-per-row with lanes splitting t.
// grid (3, NBH), block 192 = 6 warps. Warp w of group g handles rows
// r = g*6 + w + 18*j  (j = 0..31) -> uniform work per warp.
// ---------------------------------------------------------------------------
__global__ void k4b_mlstm(const float* __restrict__ on_g,
                          const float* __restrict__ on_b) {
    __shared__ float a_s[SS];               // 2.3KB
    __shared__ float4 kk[SS];               // 9.2KB
    __shared__ float4 vv[SS];               // 9.2KB
    const int grp = blockIdx.x;             // 0..2
    const int bh = blockIdx.y;
    const int b = bh / NH, n = bh % NH;
    const int tid = threadIdx.x;            // 192
    const int w = tid >> 5, lane = tid & 31;

    for (int i = tid; i < SS; i += 192) {
        a_s[i] = g_a[bh * SS + i];
        kk[i] = g_k4[bh * SS + i];
        vv[i] = g_v4[bh * SS + i];
    }
    __syncthreads();

    const float4 og = *(const float4*)(on_g + n * 4);
    const float4 ob = *(const float4*)(on_b + n * 4);
    const int rb = grp * 6 + w;              // 0..17

    for (int j = 0; j < 32; j++) {
        const int s = rb + 18 * j;
        const float2 cm = g_cm[bh * SS + s];
        const float M = cm.x, cums = cm.y;
        const float4 q4 = g_q4[bh * SS + s];

        float csum = 0.f, o0 = 0.f, o1 = 0.f, o2 = 0.f, o3 = 0.f;
        for (int t = lane; t <= s; t += 32) {
            float e = __expf(a_s[t] - M);
            float4 kt = kk[t];
            float4 vt = vv[t];
            float qk = (q4.x * kt.x + q4.y * kt.y + q4.z * kt.z + q4.w * kt.w) * 0.5f;
            float c = qk * e;
            csum += c;
            o0 += c * vt.x; o1 += c * vt.y; o2 += c * vt.z; o3 += c * vt.w;
        }
#pragma unroll
        for (int off = 16; off > 0; off >>= 1) {
            csum += __shfl_down_sync(0xffffffffu, csum, off);
            o0 += __shfl_down_sync(0xffffffffu, o0, off);
            o1 += __shfl_down_sync(0xffffffffu, o1, off);
            o2 += __shfl_down_sync(0xffffffffu, o2, off);
            o3 += __shfl_down_sync(0xffffffffu, o3, off);
        }
        if (lane == 0) {
            float norm = fmaxf(fabsf(csum), __expf(-(cums + M)));
            float inv = 1.f / (norm + 1e-6f);
            float h0 = o0 * inv, h1 = o1 * inv, h2 = o2 * inv, h3 = o3 * inv;
            float m = (h0 + h1 + h2 + h3) * 0.25f;
            float d0 = h0 - m, d1 = h1 - m, d2 = h2 - m, d3 = h3 - m;
            float var = (d0 * d0 + d1 * d1 + d2 * d2 + d3 * d3) * 0.25f;
            float r = rsqrtf(var + 1e-5f);
            float4 out = make_float4(d0 * r * og.x + ob.x,
                                     d1 * r * og.y + ob.y,
                                     d2 * r * og.z + ob.z,
                                     d3 * r * og.w + ob.w);
            *(float4*)(g_hnorm + (b * SS + s) * INNER + n * 4) = out;
        }
    }
}

// ---------------------------------------------------------------------------
// K5 v3: skip + z-gate + down-proj + residual. 8 positions per block.
// 384 threads = 48 channel-pairs (c, c+48) x 8 f-slices of 24.
// ---------------------------------------------------------------------------
__global__ void k5_down(const float* __restrict__ x,
                        const float* __restrict__ skip,
                        const float* __restrict__ w_down,
                        const float* __restrict__ b_down,
                        float* __restrict__ out) {
    __shared__ float hs[8 * INNER];         // 6KB
    __shared__ float part[8][8][96];        // 24.6KB
    const int g0 = blockIdx.x * 8;
    const int tid = threadIdx.x;            // 384
    for (int i = tid; i < 8 * INNER; i += 384) {
        int p = i / INNER, d = i % INNER;
        int g = g0 + p;
        float hn = g_hnorm[g * INNER + d];
        float xc = g_xconv[g * INNER + d];
        float z = g_xi[g * (2 * INNER) + INNER + d];
        float sg = 1.f / (1.f + __expf(-z));
        hs[i] = (hn + skip[d] * xc) * (z * sg);
    }
    __syncthreads();

    const int c = tid % 48;
    const int slice = tid / 48;             // 0..7, 24 f each
    const int f0 = slice * 24;
    const float* w0 = w_down + c * INNER + f0;
    const float* w1 = w_down + (c + 48) * INNER + f0;
    float a0[8], a1[8];
#pragma unroll
    for (int p = 0; p < 8; p++) { a0[p] = 0.f; a1[p] = 0.f; }
    for (int f = 0; f < 24; f++) {
        float wa = w0[f], wb = w1[f];
#pragma unroll
        for (int p = 0; p < 8; p++) {
            float hv = hs[p * INNER + f0 + f];
            a0[p] += wa * hv;
            a1[p] += wb * hv;
        }
    }
#pragma unroll
    for (int p = 0; p < 8; p++) { part[p][slice][c] = a0[p]; part[p][slice][c + 48] = a1[p]; }
    __syncthreads();

    const int b = g0 / SS, s0 = g0 % SS;
#pragma unroll
    for (int j = 0; j < 2; j++) {
        int idx = tid + j * 384;            // 0..767
        int c2 = idx % 96, p2 = idx / 96;
        float v = b_down[c2];
#pragma unroll
        for (int sl = 0; sl < 8; sl++) v += part[p2][sl][c2];
        int gi = (b * DIMC + c2) * SS + s0 + p2;
        out[gi] = x[gi] + v;
    }
}

// ---------------------------------------------------------------------------
extern "C" void kernel_launch(void* const* d_in, const int* in_sizes, int n_in,
                              void* d_out, int out_size) {
    const float* x      = (const float*)d_in[0];
    const float* ln_g   = (const float*)d_in[1];
    const float* ln_b   = (const float*)d_in[2];
    const float* w_up   = (const float*)d_in[3];
    const float* b_up   = (const float*)d_in[4];
    const float* w_q    = (const float*)d_in[5];
    const float* b_q    = (const float*)d_in[6];
    const float* w_k    = (const float*)d_in[7];
    const float* b_k    = (const float*)d_in[8];
    const float* w_v    = (const float*)d_in[9];
    const float* b_v    = (const float*)d_in[10];
    const float* w_conv = (const float*)d_in[11];
    const float* b_conv = (const float*)d_in[12];
    const float* w_ig   = (const float*)d_in[13];
    const float* b_ig   = (const float*)d_in[14];
    const float* w_fg   = (const float*)d_in[15];
    const float* b_fg   = (const float*)d_in[16];
    const float* on_g   = (const float*)d_in[17];
    const float* on_b   = (const float*)d_in[18];
    const float* skip   = (const float*)d_in[19];
    const float* w_down = (const float*)d_in[20];
    const float* b_down = (const float*)d_in[21];
    float* out = (float*)d_out;

    k1_ln_up<<<GTOT / 8, 384>>>(x, ln_g, ln_b, w_up, b_up);
    k23_conv_qkv<<<(GTOT * NH) / 256, 256>>>(w_conv, b_conv,
                                             w_q, b_q, w_k, b_k, w_v, b_v);
    k3b_gates<<<GTOT / 8, 384>>>(w_ig, b_ig, w_fg, b_fg);
    k4a_scan<<<NBH, SS>>>();
    k4b_mlstm<<<dim3(3, NBH), 192>>>(on_g, on_b);
    k5_down<<<GTOT / 8, 384>>>(x, skip, w_down, b_down, out);
}

// round 6
// speedup vs baseline: 1.5847x; 1.5847x over previous
#include <cuda_runtime.h>
#include <math.h>

#define BB 2
#define DIMC 96
#define INNER 192
#define NH 48
#define DH 4
#define SS 576
#define GTOT (BB*SS)   // 1152
#define F3 (3*INNER)   // 576
#define NBH (BB*NH)    // 96

// Scratch (device globals; no allocation allowed)
__device__ float g_z[GTOT * INNER];         // z half of up-proj
__device__ float g_xconv[GTOT * INNER];     // silu(causal conv)
__device__ float4 g_q4[NBH * SS];           // head-major q
__device__ float4 g_k4[NBH * SS];           // head-major k
__device__ float4 g_v4[NBH * SS];           // head-major v
__device__ float g_ig[NBH * SS];
__device__ float g_fg[NBH * SS];
__device__ float g_hnorm[GTOT * INNER];
// transposed weights
__device__ float g_wupT[DIMC * 2 * INNER];  // [c][o]  96 x 384
__device__ float g_wgT[F3 * 96];            // [f][j]  j<48: ig head j, else fg head j-48
__device__ float g_wdT[INNER * DIMC];       // [f][c]  192 x 96

// ---------------------------------------------------------------------------
// kT: weight transposes (coalesced writes; runs once per replay, trivial)
// ---------------------------------------------------------------------------
__global__ void kT(const float* __restrict__ w_up,
                   const float* __restrict__ w_ig,
                   const float* __restrict__ w_fg,
                   const float* __restrict__ w_down) {
    int i = blockIdx.x * 256 + threadIdx.x;
    // wupT: 96*384 = 36864
    if (i < DIMC * 384) {
        int c = i / 384, o = i % 384;
        g_wupT[c * 384 + o] = w_up[o * DIMC + c];
        return;
    }
    i -= DIMC * 384;
    // wgT: 576*96 = 55296
    if (i < F3 * 96) {
        int f = i / 96, j = i % 96;
        g_wgT[f * 96 + j] = (j < NH) ? w_ig[j * F3 + f] : w_fg[(j - NH) * F3 + f];
        return;
    }
    i -= F3 * 96;
    // wdT: 192*96 = 18432
    if (i < INNER * DIMC) {
        int f = i / DIMC, c = i % DIMC;
        g_wdT[f * DIMC + c] = w_down[c * INNER + f];
    }
}

// ---------------------------------------------------------------------------
// K_A: LN + up-proj (8 main positions + 3 halo) + causal conv + SiLU +
//      per-head qkv + gate pre-activations. 144 blocks x 384 threads.
// ---------------------------------------------------------------------------
__global__ void kA(const float* __restrict__ x,
                   const float* __restrict__ ln_g,
                   const float* __restrict__ ln_b,
                   const float* __restrict__ b_up,
                   const float* __restrict__ w_conv,
                   const float* __restrict__ b_conv,
                   const float* __restrict__ w_q, const float* __restrict__ b_q,
                   const float* __restrict__ w_k, const float* __restrict__ b_k,
                   const float* __restrict__ w_v, const float* __restrict__ b_v,
                   const float* __restrict__ b_ig, const float* __restrict__ b_fg) {
    __shared__ __align__(16) float h[11][100];      // 4.4KB (LN'd input)
    __shared__ float mu[11], iv[11];
    __shared__ __align__(16) float xim[11][INNER];  // 8.4KB (x_mlstm half)
    __shared__ __align__(16) float sq[8 * F3];      // 18KB  (q|k|v per position)
    __shared__ __align__(16) float part[8][4][100]; // 12.8KB (gate partials)
    const int g0 = blockIdx.x * 8;
    const int b = g0 / SS, sl0 = g0 % SS;   // blocks never straddle batches
    const int tid = threadIdx.x;            // 384
    const int wid = tid >> 5, lane = tid & 31;

    // ---- load x (11 rows: sloc = sl0-3+hp), zero-invalid
    for (int i = tid; i < 11 * DIMC; i += 384) {
        int hp = i / DIMC, c = i % DIMC;
        int sloc = sl0 - 3 + hp;
        h[hp][c] = (sloc >= 0) ? x[(b * DIMC + c) * SS + sloc] : 0.f;
    }
    __syncthreads();
    // ---- LN stats, warp per row
    if (wid < 11) {
        float sum = 0.f, sqv = 0.f;
        for (int c = lane; c < DIMC; c += 32) { float v = h[wid][c]; sum += v; sqv += v * v; }
#pragma unroll
        for (int off = 16; off > 0; off >>= 1) {
            sum += __shfl_down_sync(0xffffffffu, sum, off);
            sqv += __shfl_down_sync(0xffffffffu, sqv, off);
        }
        if (lane == 0) {
            float m = sum * (1.f / DIMC);
            float var = sqv * (1.f / DIMC) - m * m;
            mu[wid] = m;
            iv[wid] = rsqrtf(var + 1e-5f);
        }
    }
    __syncthreads();
    for (int i = tid; i < 11 * DIMC; i += 384) {
        int hp = i / DIMC, c = i % DIMC;
        h[hp][c] = (h[hp][c] - mu[hp]) * iv[hp] * ln_g[c] + ln_b[c];
    }
    __syncthreads();

    // ---- up-proj: thread o, 11 positions; coalesced transposed weights
    {
        const int o = tid;
        float acc[11];
        float bias = b_up[o];
#pragma unroll
        for (int p = 0; p < 11; p++) acc[p] = bias;
        for (int c = 0; c < DIMC; c++) {
            float w = g_wupT[c * 384 + o];
#pragma unroll
            for (int p = 0; p < 11; p++) acc[p] += w * h[p][c];
        }
        if (o < INNER) {
#pragma unroll
            for (int p = 0; p < 11; p++) xim[p][o] = acc[p];
        } else {
#pragma unroll
            for (int p = 0; p < 8; p++)
                g_z[(g0 + p) * INNER + (o - INNER)] = acc[p + 3];
        }
    }
    __syncthreads();

    // ---- conv + SiLU + qkv: thread = (p, n), 8*48 = 384
    {
        const int p = tid / NH, n = tid % NH;
        float xc[4];
#pragma unroll
        for (int d = 0; d < 4; d++) xc[d] = b_conv[n * 4 + d];
#pragma unroll
        for (int k = 0; k < 4; k++) {
            if (sl0 + p - 3 + k >= 0) {
                const float* xr = &xim[p + k][n * 4];
#pragma unroll
                for (int d = 0; d < 4; d++)
                    xc[d] += w_conv[(n * 4 + d) * 4 + k] * xr[d];
            }
        }
#pragma unroll
        for (int d = 0; d < 4; d++) {
            float sg = 1.f / (1.f + __expf(-xc[d]));
            xc[d] *= sg;
        }
        float xm0 = xim[p + 3][n * 4], xm1 = xim[p + 3][n * 4 + 1];
        float xm2 = xim[p + 3][n * 4 + 2], xm3 = xim[p + 3][n * 4 + 3];

        *(float4*)(g_xconv + (g0 + p) * INNER + n * 4) =
            make_float4(xc[0], xc[1], xc[2], xc[3]);

        float q[4], kk[4], v[4];
#pragma unroll
        for (int o = 0; o < 4; o++) {
            const float* wq = w_q + n * 16 + o * 4;
            q[o] = b_q[n * 4 + o] + wq[0] * xc[0] + wq[1] * xc[1] + wq[2] * xc[2] + wq[3] * xc[3];
            const float* wk = w_k + n * 16 + o * 4;
            kk[o] = b_k[n * 4 + o] + wk[0] * xc[0] + wk[1] * xc[1] + wk[2] * xc[2] + wk[3] * xc[3];
            const float* wv = w_v + n * 16 + o * 4;
            v[o] = b_v[n * 4 + o] + wv[0] * xm0 + wv[1] * xm1 + wv[2] * xm2 + wv[3] * xm3;
        }
        float4 qf = make_float4(q[0], q[1], q[2], q[3]);
        float4 kf = make_float4(kk[0], kk[1], kk[2], kk[3]);
        float4 vf = make_float4(v[0], v[1], v[2], v[3]);
        *(float4*)(sq + p * F3 + n * 4)             = qf;
        *(float4*)(sq + p * F3 + INNER + n * 4)     = kf;
        *(float4*)(sq + p * F3 + 2 * INNER + n * 4) = vf;
        int hidx = (b * NH + n) * SS + sl0 + p;
        g_q4[hidx] = qf;
        g_k4[hidx] = kf;
        g_v4[hidx] = vf;
    }
    __syncthreads();

    // ---- gates: 96 rows (48 ig + 48 fg) x 4 f-slices of 144
    {
        const int r = tid % 96;
        const int slice = tid / 96;
        const int f0 = slice * 144;
        float acc[8];
#pragma unroll
        for (int p = 0; p < 8; p++) acc[p] = 0.f;
        for (int f = 0; f < 144; f++) {
            float w = g_wgT[(f0 + f) * 96 + r];
#pragma unroll
            for (int p = 0; p < 8; p++) acc[p] += w * sq[p * F3 + f0 + f];
        }
#pragma unroll
        for (int p = 0; p < 8; p++) part[p][slice][r] = acc[p];
    }
    __syncthreads();
#pragma unroll
    for (int j = 0; j < 2; j++) {
        int idx = tid + j * 384;            // 0..767
        int r2 = idx % 96, p2 = idx / 96;
        float v = part[p2][0][r2] + part[p2][1][r2] + part[p2][2][r2] + part[p2][3][r2];
        bool ii = r2 < NH;
        int n2 = ii ? r2 : r2 - NH;
        v += ii ? b_ig[n2] : b_fg[n2];
        float* dst = ii ? g_ig : g_fg;
        dst[(b * NH + n2) * SS + sl0 + p2] = v;
    }
}

// ---------------------------------------------------------------------------
// K_B: per-head scan (redone per block, cheap) + mLSTM + MultiHeadLayerNorm.
// grid (3, NBH), 192 threads = 6 warps; warp handles rows rb + 18*j.
// ---------------------------------------------------------------------------
__global__ void kB(const float* __restrict__ on_g,
                   const float* __restrict__ on_b) {
    __shared__ __align__(16) float a_s[SS];    // 2.3KB
    __shared__ __align__(16) float cum_s[SS];  // 2.3KB
    __shared__ __align__(16) float M_s[SS];    // 2.3KB
    __shared__ __align__(16) float4 kk[SS];    // 9.2KB
    __shared__ __align__(16) float4 vv[SS];    // 9.2KB
    __shared__ float wsum[6], wmax[6];
    const int grp = blockIdx.x;             // 0..2
    const int bh = blockIdx.y;
    const int b = bh / NH, n = bh % NH;
    const int tid = threadIdx.x;            // 192
    const int w = tid >> 5, lane = tid & 31;

    // ---- scan: thread handles elements e0..e0+2 (576 = 3*192)
    {
        const int e0 = 3 * tid;
        float lf[3], igv[3];
#pragma unroll
        for (int i = 0; i < 3; i++) {
            float fgv = g_fg[bh * SS + e0 + i];
            igv[i] = g_ig[bh * SS + e0 + i];
            lf[i] = (fgv > 0.f) ? -log1pf(__expf(-fgv)) : (fgv - log1pf(__expf(fgv)));
        }
        float c1 = lf[0], c2 = c1 + lf[1], c3 = c2 + lf[2];
        float v = c3;
#pragma unroll
        for (int off = 1; off < 32; off <<= 1) {
            float nn = __shfl_up_sync(0xffffffffu, v, off);
            if (lane >= off) v += nn;
        }
        if (lane == 31) wsum[w] = v;
        __syncthreads();
        float wexcl = 0.f;
        for (int ww = 0; ww < w; ww++) wexcl += wsum[ww];
        float texcl = wexcl + (v - c3);
        float cums[3] = {texcl + c1, texcl + c2, texcl + c3};
        float a0 = igv[0] - cums[0], a1 = igv[1] - cums[1], a2 = igv[2] - cums[2];
        float m1 = a0, m2 = fmaxf(a0, a1), m3 = fmaxf(m2, a2);
        float mv = m3;
#pragma unroll
        for (int off = 1; off < 32; off <<= 1) {
            float nn = __shfl_up_sync(0xffffffffu, mv, off);
            if (lane >= off) mv = fmaxf(mv, nn);
        }
        float mexcl_w = __shfl_up_sync(0xffffffffu, mv, 1);
        if (lane == 0) mexcl_w = -1e30f;
        if (lane == 31) wmax[w] = mv;
        __syncthreads();
        float wexclm = -1e30f;
        for (int ww = 0; ww < w; ww++) wexclm = fmaxf(wexclm, wmax[ww]);
        float base_m = fmaxf(wexclm, mexcl_w);
        a_s[e0] = a0;        a_s[e0 + 1] = a1;        a_s[e0 + 2] = a2;
        cum_s[e0] = cums[0]; cum_s[e0 + 1] = cums[1]; cum_s[e0 + 2] = cums[2];
        M_s[e0] = fmaxf(base_m, m1);
        M_s[e0 + 1] = fmaxf(base_m, m2);
        M_s[e0 + 2] = fmaxf(base_m, m3);
    }
    for (int i = tid; i < SS; i += 192) {
        kk[i] = g_k4[bh * SS + i];
        vv[i] = g_v4[bh * SS + i];
    }
    __syncthreads();

    const float4 og = *(const float4*)(on_g + n * 4);
    const float4 ob = *(const float4*)(on_b + n * 4);
    const int rb = grp * 6 + w;              // 0..17

    for (int j = 0; j < 32; j++) {
        const int s = rb + 18 * j;
        const float M = M_s[s], cums = cum_s[s];
        const float4 q4 = g_q4[bh * SS + s];

        float csum = 0.f, o0 = 0.f, o1 = 0.f, o2 = 0.f, o3 = 0.f;
        for (int t = lane; t <= s; t += 32) {
            float e = __expf(a_s[t] - M);
            float4 kt = kk[t];
            float4 vt = vv[t];
            float qk = (q4.x * kt.x + q4.y * kt.y + q4.z * kt.z + q4.w * kt.w) * 0.5f;
            float c = qk * e;
            csum += c;
            o0 += c * vt.x; o1 += c * vt.y; o2 += c * vt.z; o3 += c * vt.w;
        }
#pragma unroll
        for (int off = 16; off > 0; off >>= 1) {
            csum += __shfl_down_sync(0xffffffffu, csum, off);
            o0 += __shfl_down_sync(0xffffffffu, o0, off);
            o1 += __shfl_down_sync(0xffffffffu, o1, off);
            o2 += __shfl_down_sync(0xffffffffu, o2, off);
            o3 += __shfl_down_sync(0xffffffffu, o3, off);
        }
        if (lane == 0) {
            float norm = fmaxf(fabsf(csum), __expf(-(cums + M)));
            float inv = 1.f / (norm + 1e-6f);
            float h0 = o0 * inv, h1 = o1 * inv, h2 = o2 * inv, h3 = o3 * inv;
            float m = (h0 + h1 + h2 + h3) * 0.25f;
            float d0 = h0 - m, d1 = h1 - m, d2 = h2 - m, d3 = h3 - m;
            float var = (d0 * d0 + d1 * d1 + d2 * d2 + d3 * d3) * 0.25f;
            float r = rsqrtf(var + 1e-5f);
            float4 out = make_float4(d0 * r * og.x + ob.x,
                                     d1 * r * og.y + ob.y,
                                     d2 * r * og.z + ob.z,
                                     d3 * r * og.w + ob.w);
            *(float4*)(g_hnorm + (b * SS + s) * INNER + n * 4) = out;
        }
    }
}

// ---------------------------------------------------------------------------
// K_C: skip + z-gate + down-proj + residual. 8 positions per block.
// 384 threads = 96 channels x 4 f-slices of 48; transposed w_down.
// ---------------------------------------------------------------------------
__global__ void kC(const float* __restrict__ x,
                   const float* __restrict__ skip,
                   const float* __restrict__ b_down,
                   float* __restrict__ out) {
    __shared__ __align__(16) float hs[8 * INNER];   // 6KB
    __shared__ __align__(16) float part[8][4][100]; // 12.8KB
    const int g0 = blockIdx.x * 8;
    const int tid = threadIdx.x;            // 384
    for (int i = tid; i < 8 * INNER; i += 384) {
        int p = i / INNER, d = i % INNER;
        int g = g0 + p;
        float hn = g_hnorm[g * INNER + d];
        float xc = g_xconv[g * INNER + d];
        float z = g_z[g * INNER + d];
        float sg = 1.f / (1.f + __expf(-z));
        hs[i] = (hn + skip[d] * xc) * (z * sg);
    }
    __syncthreads();

    const int c = tid % 96;
    const int slice = tid / 96;             // 4 slices of 48
    const int f0 = slice * 48;
    float acc[8];
#pragma unroll
    for (int p = 0; p < 8; p++) acc[p] = 0.f;
    for (int f = 0; f < 48; f++) {
        float w = g_wdT[(f0 + f) * DIMC + c];
#pragma unroll
        for (int p = 0; p < 8; p++) acc[p] += w * hs[p * INNER + f0 + f];
    }
#pragma unroll
    for (int p = 0; p < 8; p++) part[p][slice][c] = acc[p];
    __syncthreads();

    const int b = g0 / SS, s0 = g0 % SS;
#pragma unroll
    for (int j = 0; j < 2; j++) {
        int idx = tid + j * 384;            // 0..767
        int c2 = idx % 96, p2 = idx / 96;
        float v = part[p2][0][c2] + part[p2][1][c2] + part[p2][2][c2] + part[p2][3][c2]
                + b_down[c2];
        int gi = (b * DIMC + c2) * SS + s0 + p2;
        out[gi] = x[gi] + v;
    }
}

// ---------------------------------------------------------------------------
extern "C" void kernel_launch(void* const* d_in, const int* in_sizes, int n_in,
                              void* d_out, int out_size) {
    const float* x      = (const float*)d_in[0];
    const float* ln_g   = (const float*)d_in[1];
    const float* ln_b   = (const float*)d_in[2];
    const float* w_up   = (const float*)d_in[3];
    const float* b_up   = (const float*)d_in[4];
    const float* w_q    = (const float*)d_in[5];
    const float* b_q    = (const float*)d_in[6];
    const float* w_k    = (const float*)d_in[7];
    const float* b_k    = (const float*)d_in[8];
    const float* w_v    = (const float*)d_in[9];
    const float* b_v    = (const float*)d_in[10];
    const float* w_conv = (const float*)d_in[11];
    const float* b_conv = (const float*)d_in[12];
    const float* w_ig   = (const float*)d_in[13];
    const float* b_ig   = (const float*)d_in[14];
    const float* w_fg   = (const float*)d_in[15];
    const float* b_fg   = (const float*)d_in[16];
    const float* on_g   = (const float*)d_in[17];
    const float* on_b   = (const float*)d_in[18];
    const float* skip   = (const float*)d_in[19];
    const float* w_down = (const float*)d_in[20];
    const float* b_down = (const float*)d_in[21];
    float* out = (float*)d_out;

    const int ntrans = DIMC * 384 + F3 * 96 + INNER * DIMC;   // 110592
    kT<<<(ntrans + 255) / 256, 256>>>(w_up, w_ig, w_fg, w_down);
    kA<<<GTOT / 8, 384>>>(x, ln_g, ln_b, b_up, w_conv, b_conv,
                          w_q, b_q, w_k, b_k, w_v, b_v, b_ig, b_fg);
    kB<<<dim3(3, NBH), 192>>>(on_g, on_b);
    kC<<<GTOT / 8, 384>>>(x, skip, b_down, out);
}

// round 7
// speedup vs baseline: 3.0101x; 1.8995x over previous
#include <cuda_runtime.h>
#include <math.h>

#define BB 2
#define DIMC 96
#define INNER 192
#define NH 48
#define DH 4
#define SS 576
#define GTOT (BB*SS)   // 1152
#define F3 (3*INNER)   // 576
#define NBH (BB*NH)    // 96

// Scratch (device globals; no allocation allowed)
__device__ float g_z[GTOT * INNER];         // z half of up-proj
__device__ float g_xconv[GTOT * INNER];     // silu(causal conv)
__device__ float4 g_q4[NBH * SS];           // head-major q
__device__ float4 g_k4[NBH * SS];           // head-major k
__device__ float4 g_v4[NBH * SS];           // head-major v
__device__ float g_ig[NBH * SS];
__device__ float g_fg[NBH * SS];
__device__ float g_hnorm[GTOT * INNER];
// transposed weights
__device__ float g_wupT[DIMC * 2 * INNER];  // [c][o]  96 x 384
__device__ float g_wgT[F3 * 96];            // [f][j]  j<48: ig head j, else fg head j-48
__device__ float g_wdT[INNER * DIMC];       // [f][c]  192 x 96

// ---------------------------------------------------------------------------
// kT: weight transposes (coalesced writes)
// ---------------------------------------------------------------------------
__global__ void kT(const float* __restrict__ w_up,
                   const float* __restrict__ w_ig,
                   const float* __restrict__ w_fg,
                   const float* __restrict__ w_down) {
    int i = blockIdx.x * 256 + threadIdx.x;
    if (i < DIMC * 384) {
        int c = i / 384, o = i % 384;
        g_wupT[c * 384 + o] = w_up[o * DIMC + c];
        return;
    }
    i -= DIMC * 384;
    if (i < F3 * 96) {
        int f = i / 96, j = i % 96;
        g_wgT[f * 96 + j] = (j < NH) ? w_ig[j * F3 + f] : w_fg[(j - NH) * F3 + f];
        return;
    }
    i -= F3 * 96;
    if (i < INNER * DIMC) {
        int f = i / DIMC, c = i % DIMC;
        g_wdT[f * DIMC + c] = w_down[c * INNER + f];
    }
}

// ---------------------------------------------------------------------------
// K_A: LN + up-proj (4 main positions + 3 halo for x_mlstm only) + causal
// conv + SiLU + per-head qkv + gate pre-activations. 288 blocks x 384 thr.
// ---------------------------------------------------------------------------
__global__ void kA(const float* __restrict__ x,
                   const float* __restrict__ ln_g,
                   const float* __restrict__ ln_b,
                   const float* __restrict__ b_up,
                   const float* __restrict__ w_conv,
                   const float* __restrict__ b_conv,
                   const float* __restrict__ w_q, const float* __restrict__ b_q,
                   const float* __restrict__ w_k, const float* __restrict__ b_k,
                   const float* __restrict__ w_v, const float* __restrict__ b_v,
                   const float* __restrict__ b_ig, const float* __restrict__ b_fg) {
    __shared__ __align__(16) float h[7][100];       // LN'd input (7 rows)
    __shared__ float mu[7], iv[7];
    __shared__ __align__(16) float xim[7][INNER];   // x_mlstm half
    __shared__ __align__(16) float sq[4 * F3];      // q|k|v per main position
    __shared__ __align__(16) float part[4][4][100]; // gate split-K partials
    const int g0 = blockIdx.x * 4;
    const int b = g0 / SS, sl0 = g0 % SS;   // blocks never straddle batches
    const int tid = threadIdx.x;            // 384
    const int wid = tid >> 5, lane = tid & 31;

    // ---- load x (7 rows: sloc = sl0-3+hp), zero-invalid
    for (int i = tid; i < 7 * DIMC; i += 384) {
        int hp = i / DIMC, c = i % DIMC;
        int sloc = sl0 - 3 + hp;
        h[hp][c] = (sloc >= 0) ? x[(b * DIMC + c) * SS + sloc] : 0.f;
    }
    __syncthreads();
    // ---- LN stats, warp per row
    if (wid < 7) {
        float sum = 0.f, sqv = 0.f;
        for (int c = lane; c < DIMC; c += 32) { float v = h[wid][c]; sum += v; sqv += v * v; }
#pragma unroll
        for (int off = 16; off > 0; off >>= 1) {
            sum += __shfl_down_sync(0xffffffffu, sum, off);
            sqv += __shfl_down_sync(0xffffffffu, sqv, off);
        }
        if (lane == 0) {
            float m = sum * (1.f / DIMC);
            float var = sqv * (1.f / DIMC) - m * m;
            mu[wid] = m;
            iv[wid] = rsqrtf(var + 1e-5f);
        }
    }
    __syncthreads();
    for (int i = tid; i < 7 * DIMC; i += 384) {
        int hp = i / DIMC, c = i % DIMC;
        h[hp][c] = (h[hp][c] - mu[hp]) * iv[hp] * ln_g[c] + ln_b[c];
    }
    __syncthreads();

    // ---- up-proj (coalesced transposed weights)
    if (tid < INNER) {
        const int o = tid;
        float acc[7];
        float bias = b_up[o];
#pragma unroll
        for (int p = 0; p < 7; p++) acc[p] = bias;
        for (int c = 0; c < DIMC; c++) {
            float w = g_wupT[c * 384 + o];
#pragma unroll
            for (int p = 0; p < 7; p++) acc[p] += w * h[p][c];
        }
#pragma unroll
        for (int p = 0; p < 7; p++) xim[p][o] = acc[p];
    } else {
        const int o = tid;                   // 192..383 -> z channels
        float acc[4];
        float bias = b_up[o];
#pragma unroll
        for (int p = 0; p < 4; p++) acc[p] = bias;
        for (int c = 0; c < DIMC; c++) {
            float w = g_wupT[c * 384 + o];
#pragma unroll
            for (int p = 0; p < 4; p++) acc[p] += w * h[p + 3][c];
        }
#pragma unroll
        for (int p = 0; p < 4; p++)
            g_z[(g0 + p) * INNER + (o - INNER)] = acc[p];
    }
    __syncthreads();

    // ---- conv + SiLU + qkv: thread = (p, n), 4*48 = 192 active
    if (tid < 192) {
        const int p = tid / NH, n = tid % NH;
        float xc[4];
#pragma unroll
        for (int d = 0; d < 4; d++) xc[d] = b_conv[n * 4 + d];
#pragma unroll
        for (int k = 0; k < 4; k++) {
            if (sl0 + p - 3 + k >= 0) {
                const float* xr = &xim[p + k][n * 4];
#pragma unroll
                for (int d = 0; d < 4; d++)
                    xc[d] += w_conv[(n * 4 + d) * 4 + k] * xr[d];
            }
        }
#pragma unroll
        for (int d = 0; d < 4; d++) {
            float sg = 1.f / (1.f + __expf(-xc[d]));
            xc[d] *= sg;
        }
        float xm0 = xim[p + 3][n * 4], xm1 = xim[p + 3][n * 4 + 1];
        float xm2 = xim[p + 3][n * 4 + 2], xm3 = xim[p + 3][n * 4 + 3];

        *(float4*)(g_xconv + (g0 + p) * INNER + n * 4) =
            make_float4(xc[0], xc[1], xc[2], xc[3]);

        float q[4], kk[4], v[4];
#pragma unroll
        for (int o = 0; o < 4; o++) {
            const float* wq = w_q + n * 16 + o * 4;
            q[o] = b_q[n * 4 + o] + wq[0] * xc[0] + wq[1] * xc[1] + wq[2] * xc[2] + wq[3] * xc[3];
            const float* wk = w_k + n * 16 + o * 4;
            kk[o] = b_k[n * 4 + o] + wk[0] * xc[0] + wk[1] * xc[1] + wk[2] * xc[2] + wk[3] * xc[3];
            const float* wv = w_v + n * 16 + o * 4;
            v[o] = b_v[n * 4 + o] + wv[0] * xm0 + wv[1] * xm1 + wv[2] * xm2 + wv[3] * xm3;
        }
        float4 qf = make_float4(q[0], q[1], q[2], q[3]);
        float4 kf = make_float4(kk[0], kk[1], kk[2], kk[3]);
        float4 vf = make_float4(v[0], v[1], v[2], v[3]);
        *(float4*)(sq + p * F3 + n * 4)             = qf;
        *(float4*)(sq + p * F3 + INNER + n * 4)     = kf;
        *(float4*)(sq + p * F3 + 2 * INNER + n * 4) = vf;
        int hidx = (b * NH + n) * SS + sl0 + p;
        g_q4[hidx] = qf;
        g_k4[hidx] = kf;
        g_v4[hidx] = vf;
    }
    __syncthreads();

    // ---- gates: 96 rows (48 ig + 48 fg) x 4 f-slices of 144
    {
        const int r = tid % 96;
        const int slice = tid / 96;
        const int f0 = slice * 144;
        float acc[4];
#pragma unroll
        for (int p = 0; p < 4; p++) acc[p] = 0.f;
        for (int f = 0; f < 144; f++) {
            float w = g_wgT[(f0 + f) * 96 + r];
#pragma unroll
            for (int p = 0; p < 4; p++) acc[p] += w * sq[p * F3 + f0 + f];
        }
#pragma unroll
        for (int p = 0; p < 4; p++) part[p][slice][r] = acc[p];
    }
    __syncthreads();
    {
        const int r2 = tid % 96, p2 = tid / 96;   // 4*96 = 384 outputs
        float v = part[p2][0][r2] + part[p2][1][r2] + part[p2][2][r2] + part[p2][3][r2];
        bool ii = r2 < NH;
        int n2 = ii ? r2 : r2 - NH;
        v += ii ? b_ig[n2] : b_fg[n2];
        float* dst = ii ? g_ig : g_fg;
        dst[(b * NH + n2) * SS + sl0 + p2] = v;
    }
}

// ---------------------------------------------------------------------------
// K_B: mLSTM as linear-attention prefix sum. One block per (b,head),
// 576 threads (thread = position).
//   a[t] = ig[t] - cums[t];  A = max_t a;  E[t] = 0.5*exp(a[t]-A)
//   state (20 floats) = inclusive prefix of (E*k⊗v, E*k)
//   o = q·S, csum = q·n;  denom = max(|csum|, exp(-(cums+A))) + 1e-6*exp(M-A)
// ---------------------------------------------------------------------------
__global__ void kB(const float* __restrict__ on_g,
                   const float* __restrict__ on_b) {
    __shared__ float wsum[18], wmax[18], A_sh;
    __shared__ float wtot[18][20];
    __shared__ float epre[18][20];
    const int bh = blockIdx.x;
    const int b = bh / NH, n = bh % NH;
    const int s = threadIdx.x;               // 576
    const int wid = s >> 5, lane = s & 31;

    // ---- scans: cums (sum of logsigmoid fg), a, prefix-max M, total max A
    float fgv = g_fg[bh * SS + s];
    float igv = g_ig[bh * SS + s];
    float lf = (fgv > 0.f) ? -log1pf(__expf(-fgv)) : (fgv - log1pf(__expf(fgv)));
    float v = lf;
#pragma unroll
    for (int off = 1; off < 32; off <<= 1) {
        float nn = __shfl_up_sync(0xffffffffu, v, off);
        if (lane >= off) v += nn;
    }
    if (lane == 31) wsum[wid] = v;
    __syncthreads();
    float wex = 0.f;
    for (int ww = 0; ww < wid; ww++) wex += wsum[ww];
    const float cums = v + wex;
    const float a = igv - cums;
    float m = a;
#pragma unroll
    for (int off = 1; off < 32; off <<= 1) {
        float nn = __shfl_up_sync(0xffffffffu, m, off);
        if (lane >= off) m = fmaxf(m, nn);
    }
    if (lane == 31) wmax[wid] = m;
    __syncthreads();
    float wexm = -1e30f;
    for (int ww = 0; ww < wid; ww++) wexm = fmaxf(wexm, wmax[ww]);
    const float M = fmaxf(m, wexm);
    if (s == SS - 1) A_sh = M;
    __syncthreads();
    const float A = A_sh;
    const float E = 0.5f * __expf(a - A);     // 0.5 = DH^-0.5 folded in

    // ---- per-position outer product
    float4 q4 = g_q4[bh * SS + s];
    float4 k4 = g_k4[bh * SS + s];
    float4 v4 = g_v4[bh * SS + s];
    float kv[4] = {k4.x, k4.y, k4.z, k4.w};
    float vv[4] = {v4.x, v4.y, v4.z, v4.w};
    float st[20];
#pragma unroll
    for (int j = 0; j < 4; j++) {
        float ek = E * kv[j];
        st[16 + j] = ek;
#pragma unroll
        for (int d = 0; d < 4; d++) st[j * 4 + d] = ek * vv[d];
    }

    // ---- 20-component inclusive block scan
#pragma unroll
    for (int off = 1; off < 32; off <<= 1) {
        float tmp[20];
#pragma unroll
        for (int c = 0; c < 20; c++) tmp[c] = __shfl_up_sync(0xffffffffu, st[c], off);
        if (lane >= off) {
#pragma unroll
            for (int c = 0; c < 20; c++) st[c] += tmp[c];
        }
    }
    if (lane == 31) {
#pragma unroll
        for (int c = 0; c < 20; c++) wtot[wid][c] = st[c];
    }
    __syncthreads();
    if (wid == 0 && lane < 20) {
        float acc = 0.f;
        for (int ww = 0; ww < 18; ww++) { epre[ww][lane] = acc; acc += wtot[ww][lane]; }
    }
    __syncthreads();
#pragma unroll
    for (int c = 0; c < 20; c++) st[c] += epre[wid][c];

    // ---- epilogue
    float qv[4] = {q4.x, q4.y, q4.z, q4.w};
    float o[4] = {0.f, 0.f, 0.f, 0.f};
    float csum = 0.f;
#pragma unroll
    for (int j = 0; j < 4; j++) {
        csum += qv[j] * st[16 + j];
#pragma unroll
        for (int d = 0; d < 4; d++) o[d] += qv[j] * st[j * 4 + d];
    }
    float norm = fmaxf(fabsf(csum), __expf(-(cums + A)));
    float denom = norm + 1e-6f * __expf(M - A);
    float inv = 1.f / denom;
    float h0 = o[0] * inv, h1 = o[1] * inv, h2 = o[2] * inv, h3 = o[3] * inv;

    float mm = (h0 + h1 + h2 + h3) * 0.25f;
    float d0 = h0 - mm, d1 = h1 - mm, d2 = h2 - mm, d3 = h3 - mm;
    float var = (d0 * d0 + d1 * d1 + d2 * d2 + d3 * d3) * 0.25f;
    float r = rsqrtf(var + 1e-5f);
    float4 og = *(const float4*)(on_g + n * 4);
    float4 ob = *(const float4*)(on_b + n * 4);
    float4 out = make_float4(d0 * r * og.x + ob.x,
                             d1 * r * og.y + ob.y,
                             d2 * r * og.z + ob.z,
                             d3 * r * og.w + ob.w);
    *(float4*)(g_hnorm + (b * SS + s) * INNER + n * 4) = out;
}

// ---------------------------------------------------------------------------
// K_C: skip + z-gate + down-proj + residual. 4 positions per block,
// 288 blocks x 384 threads = 96 channels x 4 f-slices of 48.
// ---------------------------------------------------------------------------
__global__ void kC(const float* __restrict__ x,
                   const float* __restrict__ skip,
                   const float* __restrict__ b_down,
                   float* __restrict__ out) {
    __shared__ __align__(16) float hs[4 * INNER];
    __shared__ __align__(16) float part[4][4][100];
    const int g0 = blockIdx.x * 4;
    const int tid = threadIdx.x;            // 384
    for (int i = tid; i < 4 * INNER; i += 384) {
        int p = i / INNER, d = i % INNER;
        int g = g0 + p;
        float hn = g_hnorm[g * INNER + d];
        float xc = g_xconv[g * INNER + d];
        float z = g_z[g * INNER + d];
        float sg = 1.f / (1.f + __expf(-z));
        hs[i] = (hn + skip[d] * xc) * (z * sg);
    }
    __syncthreads();

    const int c = tid % 96;
    const int slice = tid / 96;             // 4 slices of 48
    const int f0 = slice * 48;
    float acc[4];
#pragma unroll
    for (int p = 0; p < 4; p++) acc[p] = 0.f;
    for (int f = 0; f < 48; f++) {
        float w = g_wdT[(f0 + f) * DIMC + c];
#pragma unroll
        for (int p = 0; p < 4; p++) acc[p] += w * hs[p * INNER + f0 + f];
    }
#pragma unroll
    for (int p = 0; p < 4; p++) part[p][slice][c] = acc[p];
    __syncthreads();

    const int b = g0 / SS, s0 = g0 % SS;
    {
        const int c2 = tid % 96, p2 = tid / 96;   // 384 outputs, 1/thread
        float v = part[p2][0][c2] + part[p2][1][c2] + part[p2][2][c2] + part[p2][3][c2]
                + b_down[c2];
        int gi = (b * DIMC + c2) * SS + s0 + p2;
        out[gi] = x[gi] + v;
    }
}

// ---------------------------------------------------------------------------
extern "C" void kernel_launch(void* const* d_in, const int* in_sizes, int n_in,
                              void* d_out, int out_size) {
    const float* x      = (const float*)d_in[0];
    const float* ln_g   = (const float*)d_in[1];
    const float* ln_b   = (const float*)d_in[2];
    const float* w_up   = (const float*)d_in[3];
    const float* b_up   = (const float*)d_in[4];
    const float* w_q    = (const float*)d_in[5];
    const float* b_q    = (const float*)d_in[6];
    const float* w_k    = (const float*)d_in[7];
    const float* b_k    = (const float*)d_in[8];
    const float* w_v    = (const float*)d_in[9];
    const float* b_v    = (const float*)d_in[10];
    const float* w_conv = (const float*)d_in[11];
    const float* b_conv = (const float*)d_in[12];
    const float* w_ig   = (const float*)d_in[13];
    const float* b_ig   = (const float*)d_in[14];
    const float* w_fg   = (const float*)d_in[15];
    const float* b_fg   = (const float*)d_in[16];
    const float* on_g   = (const float*)d_in[17];
    const float* on_b   = (const float*)d_in[18];
    const float* skip   = (const float*)d_in[19];
    const float* w_down = (const float*)d_in[20];
    const float* b_down = (const float*)d_in[21];
    float* out = (float*)d_out;

    const int ntrans = DIMC * 384 + F3 * 96 + INNER * DIMC;   // 110592
    kT<<<(ntrans + 255) / 256, 256>>>(w_up, w_ig, w_fg, w_down);
    kA<<<GTOT / 4, 384>>>(x, ln_g, ln_b, b_up, w_conv, b_conv,
                          w_q, b_q, w_k, b_k, w_v, b_v, b_ig, b_fg);
    kB<<<NBH, SS>>>(on_g, on_b);
    kC<<<GTOT / 4, 384>>>(x, skip, b_down, out);
}